// round 1
// baseline (speedup 1.0000x reference)
#include <cuda_runtime.h>
#include <cuda_bf16.h>
#include <cstdint>

#define BSZ 4
#define SEQ 2048
#define EMB 1024
#define HD  64

// Scratch (no cudaMalloc allowed)
__device__ float g_q[BSZ * SEQ * HD];
__device__ float g_k[BSZ * SEQ * HD];
__device__ float g_v[BSZ * SEQ * HD];
__device__ float g_vmean[BSZ * HD];

// ---------------------------------------------------------------------------
// Kernel 1: fused QKV projection.  q/k/v[row][h] = sum_e x[row][e] * W[h][e]
// M = B*S = 8192 rows, K = 1024, N = 64 per weight.  blockIdx.y selects q/k/v.
// 64x64 output tile per block, BK=16, 256 threads, 4x4 frags per thread.
// ---------------------------------------------------------------------------
__global__ __launch_bounds__(256) void qkv_kernel(
    const float* __restrict__ x,
    const float* __restrict__ Wq,
    const float* __restrict__ Wk,
    const float* __restrict__ Wv)
{
    const int which = blockIdx.y;
    const float* W = (which == 0) ? Wq : (which == 1) ? Wk : Wv;
    float* outp    = (which == 0) ? g_q : (which == 1) ? g_k : g_v;
    const int row0 = blockIdx.x * 64;

    __shared__ float sX[16][65];   // [kk][row]
    __shared__ float sW[16][65];   // [kk][head]

    const int tid = threadIdx.x;
    const int tx = tid & 15, ty = tid >> 4;

    float acc[4][4];
#pragma unroll
    for (int r = 0; r < 4; r++)
#pragma unroll
        for (int c = 0; c < 4; c++) acc[r][c] = 0.f;

    for (int k0 = 0; k0 < EMB; k0 += 16) {
#pragma unroll
        for (int u = 0; u < 4; u++) {
            int idx = tid + u * 256;          // 0..1023
            int r = idx >> 4, kk = idx & 15;
            sX[kk][r] = x[(size_t)(row0 + r) * EMB + k0 + kk];
            sW[kk][r] = W[(size_t)r * EMB + k0 + kk];   // r = head index
        }
        __syncthreads();
#pragma unroll
        for (int kk = 0; kk < 16; kk++) {
            float a[4], b[4];
#pragma unroll
            for (int r = 0; r < 4; r++) a[r] = sX[kk][ty * 4 + r];
#pragma unroll
            for (int c = 0; c < 4; c++) b[c] = sW[kk][tx * 4 + c];
#pragma unroll
            for (int r = 0; r < 4; r++)
#pragma unroll
                for (int c = 0; c < 4; c++)
                    acc[r][c] = fmaf(a[r], b[c], acc[r][c]);
        }
        __syncthreads();
    }

#pragma unroll
    for (int r = 0; r < 4; r++)
#pragma unroll
        for (int c = 0; c < 4; c++)
            outp[(size_t)(row0 + ty * 4 + r) * HD + tx * 4 + c] = acc[r][c];
}

// ---------------------------------------------------------------------------
// Kernel 2: per-batch mean of V rows (for fully-masked rows: reference softmax
// over all-(-1e9) scores is uniform over ALL 2048 keys -> out = mean(V)).
// ---------------------------------------------------------------------------
__global__ __launch_bounds__(256) void vmean_kernel()
{
    const int b = blockIdx.x;
    const int d = threadIdx.x & 63;
    const int chunk = threadIdx.x >> 6;     // 0..3
    float s = 0.f;
    const int i0 = chunk * (SEQ / 4);
    for (int i = i0; i < i0 + SEQ / 4; i++)
        s += g_v[((size_t)b * SEQ + i) * HD + d];
    __shared__ float red[256];
    red[threadIdx.x] = s;
    __syncthreads();
    if (chunk == 0) {
        float tot = red[d] + red[64 + d] + red[128 + d] + red[192 + d];
        g_vmean[b * HD + d] = tot * (1.0f / SEQ);
    }
}

// ---------------------------------------------------------------------------
// Kernel 3: flash attention, fp32. 64 query rows x 64 key cols per tile.
// grid = (32 qtiles, 4 batches), 256 threads (16x16), 4x4 frags.
// Masked scores carried as exactly -1e9 * 0.125 so degenerate (all-masked)
// prefixes accumulate uniformly and are later overridden by vmean.
// ---------------------------------------------------------------------------
#define LDW 65
#define ATTN_SMEM (4 * 64 * LDW * 4)

__global__ __launch_bounds__(256) void attn_kernel(
    const int* __restrict__ pad, float* __restrict__ out)
{
    const int b  = blockIdx.y;
    const int qt = blockIdx.x;
    const int q0 = qt * 64;
    const int tid = threadIdx.x;
    const int tx = tid & 15, ty = tid >> 4;

    extern __shared__ float smem[];
    float* sQ = smem;                 // [64][LDW]
    float* sK = sQ + 64 * LDW;
    float* sV = sK + 64 * LDW;
    float* sP = sV + 64 * LDW;
    __shared__ int sPad[64];

    // Load Q tile (float4 from gmem, scalar stores into padded smem)
    {
        const float* qbase = g_q + ((size_t)b * SEQ + q0) * HD;
#pragma unroll
        for (int u = 0; u < 4; u++) {
            int idx = tid + u * 256;          // float4 index 0..1023
            int r = idx >> 4, f = idx & 15;
            float4 v4 = reinterpret_cast<const float4*>(qbase)[r * 16 + f];
            float* dst = sQ + r * LDW + f * 4;
            dst[0] = v4.x; dst[1] = v4.y; dst[2] = v4.z; dst[3] = v4.w;
        }
    }

    float m[4], l[4], o[4][4];
#pragma unroll
    for (int r = 0; r < 4; r++) {
        m[r] = -3.0e38f; l[r] = 0.f;
#pragma unroll
        for (int c = 0; c < 4; c++) o[r][c] = 0.f;
    }

    for (int kt = 0; kt <= qt; kt++) {
        const int k0 = kt * 64;
        __syncthreads();   // previous iteration's sK/sV/sP reads done

        const float* kbase = g_k + ((size_t)b * SEQ + k0) * HD;
        const float* vbase = g_v + ((size_t)b * SEQ + k0) * HD;
#pragma unroll
        for (int u = 0; u < 4; u++) {
            int idx = tid + u * 256;
            int r = idx >> 4, f = idx & 15;
            float4 k4 = reinterpret_cast<const float4*>(kbase)[r * 16 + f];
            float4 v4 = reinterpret_cast<const float4*>(vbase)[r * 16 + f];
            float* dk = sK + r * LDW + f * 4;
            dk[0] = k4.x; dk[1] = k4.y; dk[2] = k4.z; dk[3] = k4.w;
            float* dv = sV + r * LDW + f * 4;
            dv[0] = v4.x; dv[1] = v4.y; dv[2] = v4.z; dv[3] = v4.w;
        }
        if (tid < 64) sPad[tid] = pad[b * SEQ + k0 + tid];
        __syncthreads();

        // S = Q K^T fragment
        float s[4][4];
#pragma unroll
        for (int r = 0; r < 4; r++)
#pragma unroll
            for (int c = 0; c < 4; c++) s[r][c] = 0.f;
#pragma unroll 16
        for (int d = 0; d < 64; d++) {
            float a[4], bb[4];
#pragma unroll
            for (int r = 0; r < 4; r++) a[r] = sQ[(ty * 4 + r) * LDW + d];
#pragma unroll
            for (int c = 0; c < 4; c++) bb[c] = sK[(tx * 4 + c) * LDW + d];
#pragma unroll
            for (int r = 0; r < 4; r++)
#pragma unroll
                for (int c = 0; c < 4; c++)
                    s[r][c] = fmaf(a[r], bb[c], s[r][c]);
        }

        // mask (causal + padding, value -1e9 BEFORE the 1/sqrt(64) scale)
#pragma unroll
        for (int r = 0; r < 4; r++) {
            const int qi = q0 + ty * 4 + r;
#pragma unroll
            for (int c = 0; c < 4; c++) {
                const int kj = k0 + tx * 4 + c;
                const bool masked = (kj > qi) || (sPad[tx * 4 + c] == 0);
                float sv = masked ? -1e9f : s[r][c];
                s[r][c] = sv * 0.125f;
            }
        }

        // online softmax (row reductions across tx via shfl within 16-lane group)
#pragma unroll
        for (int r = 0; r < 4; r++) {
            float tm = fmaxf(fmaxf(s[r][0], s[r][1]), fmaxf(s[r][2], s[r][3]));
            tm = fmaxf(tm, __shfl_xor_sync(0xffffffffu, tm, 1));
            tm = fmaxf(tm, __shfl_xor_sync(0xffffffffu, tm, 2));
            tm = fmaxf(tm, __shfl_xor_sync(0xffffffffu, tm, 4));
            tm = fmaxf(tm, __shfl_xor_sync(0xffffffffu, tm, 8));
            const float mnew  = fmaxf(m[r], tm);
            const float scale = __expf(m[r] - mnew);
            float p[4];
#pragma unroll
            for (int c = 0; c < 4; c++) p[c] = __expf(s[r][c] - mnew);
            float tl = p[0] + p[1] + p[2] + p[3];
            tl += __shfl_xor_sync(0xffffffffu, tl, 1);
            tl += __shfl_xor_sync(0xffffffffu, tl, 2);
            tl += __shfl_xor_sync(0xffffffffu, tl, 4);
            tl += __shfl_xor_sync(0xffffffffu, tl, 8);
            l[r] = l[r] * scale + tl;
            m[r] = mnew;
#pragma unroll
            for (int c = 0; c < 4; c++) o[r][c] *= scale;
#pragma unroll
            for (int c = 0; c < 4; c++)
                sP[(ty * 4 + r) * LDW + tx * 4 + c] = p[c];
        }
        __syncthreads();

        // O += P V
#pragma unroll 8
        for (int j = 0; j < 64; j++) {
            float pa[4], vb[4];
#pragma unroll
            for (int r = 0; r < 4; r++) pa[r] = sP[(ty * 4 + r) * LDW + j];
#pragma unroll
            for (int c = 0; c < 4; c++) vb[c] = sV[j * LDW + tx * 4 + c];
#pragma unroll
            for (int r = 0; r < 4; r++)
#pragma unroll
                for (int c = 0; c < 4; c++)
                    o[r][c] = fmaf(pa[r], vb[c], o[r][c]);
        }
    }

    // epilogue: degenerate rows (all keys masked -> m == -1e9/8) get vmean
    float* obase = out + ((size_t)b * SEQ + q0) * HD;
#pragma unroll
    for (int r = 0; r < 4; r++) {
        const bool degen = (m[r] <= -1.0e8f);
        const float invl = 1.0f / l[r];
#pragma unroll
        for (int c = 0; c < 4; c++) {
            float val = degen ? g_vmean[b * HD + tx * 4 + c] : o[r][c] * invl;
            obase[(ty * 4 + r) * HD + tx * 4 + c] = val;
        }
    }
}

// ---------------------------------------------------------------------------
extern "C" void kernel_launch(void* const* d_in, const int* in_sizes, int n_in,
                              void* d_out, int out_size)
{
    const float* x   = (const float*)d_in[0];
    const int*   pad = (const int*)  d_in[1];
    const float* Wq  = (const float*)d_in[2];
    const float* Wk  = (const float*)d_in[3];
    const float* Wv  = (const float*)d_in[4];
    float* out = (float*)d_out;

    cudaFuncSetAttribute(attn_kernel,
                         cudaFuncAttributeMaxDynamicSharedMemorySize, ATTN_SMEM);

    qkv_kernel<<<dim3((BSZ * SEQ) / 64, 3), 256>>>(x, Wq, Wk, Wv);
    vmean_kernel<<<BSZ, 256>>>();
    attn_kernel<<<dim3(SEQ / 64, BSZ), 256, ATTN_SMEM>>>(pad, out);
}

// round 3
// speedup vs baseline: 1.0818x; 1.0818x over previous
#include <cuda_runtime.h>
#include <cuda_bf16.h>
#include <cstdint>

#define BSZ 4
#define SEQ 2048
#define EMB 1024
#define HD  64

__device__ float g_q[BSZ * SEQ * HD];
__device__ float g_k[BSZ * SEQ * HD];
__device__ float g_v[BSZ * SEQ * HD];
__device__ float g_vmean[BSZ * HD];

// ---- packed f32x2 helpers (Blackwell FFMA2 path) --------------------------
typedef unsigned long long u64;

__device__ __forceinline__ u64 splat2(float x) {
    u64 r;
    asm("mov.b64 %0, {%1, %1};" : "=l"(r) : "f"(x));
    return r;
}
__device__ __forceinline__ void fma2(u64& d, u64 a, u64 b) {
    asm("fma.rn.f32x2 %0, %1, %2, %0;" : "+l"(d) : "l"(a), "l"(b));
}
__device__ __forceinline__ void mul2(u64& d, u64 s) {
    asm("mul.rn.f32x2 %0, %0, %1;" : "+l"(d) : "l"(s));
}
__device__ __forceinline__ void unpack2(u64 v, float& lo, float& hi) {
    asm("mov.b64 {%0, %1}, %2;" : "=f"(lo), "=f"(hi) : "l"(v));
}

// ---------------------------------------------------------------------------
// Kernel 1: QKV projection with f32x2.  128x64 tile, 128 threads, frag 4x16.
// smem staged transposed: sX[kk][row], sW[kk][head]  (rows contiguous).
// ---------------------------------------------------------------------------
#define PX 128   // sX row pitch (floats)
#define PW 64

__global__ __launch_bounds__(128) void qkv_kernel(
    const float* __restrict__ x,
    const float* __restrict__ Wq,
    const float* __restrict__ Wk,
    const float* __restrict__ Wv)
{
    const int which = blockIdx.y;
    const float* W = (which == 0) ? Wq : (which == 1) ? Wk : Wv;
    float* outp    = (which == 0) ? g_q : (which == 1) ? g_k : g_v;
    const int row0 = blockIdx.x * 128;

    __shared__ float sX[16 * PX];
    __shared__ float sW[16 * PW];

    const int tid = threadIdx.x;
    const int tx = tid & 3;        // 4 col-groups of 16
    const int ty = tid >> 2;       // 32 row-groups of 4

    u64 acc[4][8];
#pragma unroll
    for (int r = 0; r < 4; r++)
#pragma unroll
        for (int c = 0; c < 8; c++) acc[r][c] = 0ULL;

    for (int k0 = 0; k0 < EMB; k0 += 16) {
        __syncthreads();
        // stage sX: 128 rows x 16 kk, transposed store
#pragma unroll
        for (int u = 0; u < 4; u++) {
            int idx = tid + u * 128;          // 0..511 float4s
            int r = idx >> 2, f = (idx & 3) * 4;
            float4 v4 = *reinterpret_cast<const float4*>(
                &x[(size_t)(row0 + r) * EMB + k0 + f]);
            sX[(f + 0) * PX + r] = v4.x;
            sX[(f + 1) * PX + r] = v4.y;
            sX[(f + 2) * PX + r] = v4.z;
            sX[(f + 3) * PX + r] = v4.w;
        }
        // stage sW: 64 heads x 16 kk
#pragma unroll
        for (int u = 0; u < 2; u++) {
            int idx = tid + u * 128;          // 0..255 float4s
            int h = idx >> 2, f = (idx & 3) * 4;
            float4 v4 = *reinterpret_cast<const float4*>(
                &W[(size_t)h * EMB + k0 + f]);
            sW[(f + 0) * PW + h] = v4.x;
            sW[(f + 1) * PW + h] = v4.y;
            sW[(f + 2) * PW + h] = v4.z;
            sW[(f + 3) * PW + h] = v4.w;
        }
        __syncthreads();

#pragma unroll
        for (int kk = 0; kk < 16; kk++) {
            float4 a4 = *reinterpret_cast<const float4*>(&sX[kk * PX + ty * 4]);
            u64 a2[4];
            a2[0] = splat2(a4.x); a2[1] = splat2(a4.y);
            a2[2] = splat2(a4.z); a2[3] = splat2(a4.w);
#pragma unroll
            for (int g = 0; g < 4; g++) {
                ulonglong2 vb = *reinterpret_cast<const ulonglong2*>(
                    &sW[kk * PW + tx * 16 + g * 4]);
#pragma unroll
                for (int r = 0; r < 4; r++) {
                    fma2(acc[r][g * 2 + 0], a2[r], vb.x);
                    fma2(acc[r][g * 2 + 1], a2[r], vb.y);
                }
            }
        }
    }

#pragma unroll
    for (int r = 0; r < 4; r++) {
        const size_t row = row0 + ty * 4 + r;
#pragma unroll
        for (int g = 0; g < 4; g++) {
            float4 o4;
            unpack2(acc[r][g * 2 + 0], o4.x, o4.y);
            unpack2(acc[r][g * 2 + 1], o4.z, o4.w);
            *reinterpret_cast<float4*>(&outp[row * HD + tx * 16 + g * 4]) = o4;
        }
    }
}

// ---------------------------------------------------------------------------
// Kernel 2: per-batch mean of V rows (fully-masked-row fallback).
// ---------------------------------------------------------------------------
__global__ __launch_bounds__(256) void vmean_kernel()
{
    const int b = blockIdx.x;
    const int d = threadIdx.x & 63;
    const int chunk = threadIdx.x >> 6;
    float s = 0.f;
    const int i0 = chunk * (SEQ / 4);
    for (int i = i0; i < i0 + SEQ / 4; i++)
        s += g_v[((size_t)b * SEQ + i) * HD + d];
    __shared__ float red[256];
    red[threadIdx.x] = s;
    __syncthreads();
    if (chunk == 0)
        g_vmean[b * HD + d] =
            (red[d] + red[64 + d] + red[128 + d] + red[192 + d]) * (1.0f / SEQ);
}

// ---------------------------------------------------------------------------
// Kernel 3: flash attention with f32x2.
// 32-row q-tiles x 128-col k-tiles, 128 threads, heavy-first block order.
// sQt[d][row], sKt[d][key] transposed; sV[key][d]; sPt[key][row].
// ---------------------------------------------------------------------------
#define PQ 36     // sQt pitch (rows 32 + pad, 16B multiple)
#define PK 136    // sKt pitch (keys 128 + pad)
#define PV_ 68    // sV  pitch
#define PP 36     // sPt pitch

#define SM_QT 0
#define SM_KT (SM_QT + 64 * PQ)
#define SM_V  (SM_KT + 64 * PK)
#define SM_PT (SM_V + 128 * PV_)
#define ATTN_SMEM ((SM_PT + 128 * PP) * 4)

__global__ __launch_bounds__(128) void attn_kernel(
    const int* __restrict__ pad, float* __restrict__ out)
{
    const int b  = blockIdx.x & 3;
    const int jq = 63 - (blockIdx.x >> 2);     // heavy q-tiles launch first
    const int q0 = jq * 32;
    const int tid = threadIdx.x;
    const int tx = tid & 15;      // 16 col-groups
    const int ty = tid >> 4;      // 8 row-groups of 4

    extern __shared__ float smem[];
    float* sQt = smem + SM_QT;
    float* sKt = smem + SM_KT;
    float* sV  = smem + SM_V;
    float* sPt = smem + SM_PT;
    __shared__ int sPad[128];

    // stage Q transposed: sQt[d][row]
#pragma unroll
    for (int u = 0; u < 4; u++) {
        int idx = tid + u * 128;               // 0..511 float4s
        int r = idx >> 4, f = (idx & 15) * 4;
        float4 v4 = *reinterpret_cast<const float4*>(
            &g_q[((size_t)b * SEQ + q0 + r) * HD + f]);
        sQt[(f + 0) * PQ + r] = v4.x;
        sQt[(f + 1) * PQ + r] = v4.y;
        sQt[(f + 2) * PQ + r] = v4.z;
        sQt[(f + 3) * PQ + r] = v4.w;
    }

    float m[4], l[4];
    u64 o2[4][2];
#pragma unroll
    for (int r = 0; r < 4; r++) {
        m[r] = -3.0e38f; l[r] = 0.f;
        o2[r][0] = 0ULL; o2[r][1] = 0ULL;
    }

    const int nkt = (q0 + 31) / 128 + 1;
    for (int kt = 0; kt < nkt; kt++) {
        const int k0 = kt * 128;
        __syncthreads();

        // stage K transposed: thread = key, loop d. sKt[d][key]
        {
            const float* kb = &g_k[((size_t)b * SEQ + k0 + tid) * HD];
#pragma unroll
            for (int u = 0; u < 16; u++) {
                float4 v4 = *reinterpret_cast<const float4*>(&kb[u * 4]);
                sKt[(u * 4 + 0) * PK + tid] = v4.x;
                sKt[(u * 4 + 1) * PK + tid] = v4.y;
                sKt[(u * 4 + 2) * PK + tid] = v4.z;
                sKt[(u * 4 + 3) * PK + tid] = v4.w;
            }
        }
        // stage V row-major (coalesced): 128 keys x 64 dims = 2048 float4s
#pragma unroll
        for (int u = 0; u < 16; u++) {
            int idx = tid + u * 128;           // 0..2047 float4s
            int r = idx >> 4, f = (idx & 15) * 4;
            float4 v4 = *reinterpret_cast<const float4*>(
                &g_v[((size_t)b * SEQ + k0 + r) * HD + f]);
            *reinterpret_cast<float4*>(&sV[r * PV_ + f]) = v4;
        }
        sPad[tid] = pad[b * SEQ + k0 + tid];
        __syncthreads();

        // S = Q K^T  (32 x 128), frag 4 rows x 4 key-pairs (8 cols)
        u64 s2[4][4];
#pragma unroll
        for (int r = 0; r < 4; r++)
#pragma unroll
            for (int i = 0; i < 4; i++) s2[r][i] = 0ULL;
#pragma unroll 8
        for (int d = 0; d < 64; d++) {
            float4 a4 = *reinterpret_cast<const float4*>(&sQt[d * PQ + ty * 4]);
            u64 a2[4];
            a2[0] = splat2(a4.x); a2[1] = splat2(a4.y);
            a2[2] = splat2(a4.z); a2[3] = splat2(a4.w);
#pragma unroll
            for (int i = 0; i < 4; i++) {
                u64 b2 = *reinterpret_cast<const u64*>(
                    &sKt[d * PK + 2 * (tx + 16 * i)]);
#pragma unroll
                for (int r = 0; r < 4; r++) fma2(s2[r][i], a2[r], b2);
            }
        }

        // mask + online softmax, write P transposed: sPt[key][row]
#pragma unroll
        for (int r = 0; r < 4; r++) {
            const int row = ty * 4 + r;
            const int qi = q0 + row;
            float sv[8];
#pragma unroll
            for (int i = 0; i < 4; i++) {
                const int p = tx + 16 * i;
                float lo, hi; unpack2(s2[r][i], lo, hi);
                const int c0 = 2 * p, c1 = 2 * p + 1;
                bool m0 = (k0 + c0 > qi) || (sPad[c0] == 0);
                bool m1 = (k0 + c1 > qi) || (sPad[c1] == 0);
                sv[2 * i + 0] = (m0 ? -1e9f : lo) * 0.125f;
                sv[2 * i + 1] = (m1 ? -1e9f : hi) * 0.125f;
            }
            float tm = sv[0];
#pragma unroll
            for (int i = 1; i < 8; i++) tm = fmaxf(tm, sv[i]);
            tm = fmaxf(tm, __shfl_xor_sync(0xffffffffu, tm, 1));
            tm = fmaxf(tm, __shfl_xor_sync(0xffffffffu, tm, 2));
            tm = fmaxf(tm, __shfl_xor_sync(0xffffffffu, tm, 4));
            tm = fmaxf(tm, __shfl_xor_sync(0xffffffffu, tm, 8));
            const float mnew = fmaxf(m[r], tm);
            const float scale = __expf(m[r] - mnew);
            float tl = 0.f;
            float p8[8];
#pragma unroll
            for (int i = 0; i < 8; i++) { p8[i] = __expf(sv[i] - mnew); tl += p8[i]; }
            tl += __shfl_xor_sync(0xffffffffu, tl, 1);
            tl += __shfl_xor_sync(0xffffffffu, tl, 2);
            tl += __shfl_xor_sync(0xffffffffu, tl, 4);
            tl += __shfl_xor_sync(0xffffffffu, tl, 8);
            l[r] = l[r] * scale + tl;
            m[r] = mnew;
            u64 sc2 = splat2(scale);
            mul2(o2[r][0], sc2);
            mul2(o2[r][1], sc2);
#pragma unroll
            for (int i = 0; i < 4; i++) {
                const int p = tx + 16 * i;
                sPt[(2 * p + 0) * PP + row] = p8[2 * i + 0];
                sPt[(2 * p + 1) * PP + row] = p8[2 * i + 1];
            }
        }
        __syncthreads();

        // O += P V  (32 x 64), frag 4 rows x 2 col-pairs
#pragma unroll 8
        for (int j = 0; j < 128; j++) {
            float4 p4 = *reinterpret_cast<const float4*>(&sPt[j * PP + ty * 4]);
            u64 p2[4];
            p2[0] = splat2(p4.x); p2[1] = splat2(p4.y);
            p2[2] = splat2(p4.z); p2[3] = splat2(p4.w);
            ulonglong2 v2 = *reinterpret_cast<const ulonglong2*>(&sV[j * PV_ + tx * 4]);
#pragma unroll
            for (int r = 0; r < 4; r++) {
                fma2(o2[r][0], p2[r], v2.x);
                fma2(o2[r][1], p2[r], v2.y);
            }
        }
    }

    // epilogue
#pragma unroll
    for (int r = 0; r < 4; r++) {
        const int row = ty * 4 + r;
        const bool degen = (m[r] <= -1.0e8f);
        const float invl = 1.0f / l[r];
        float4 o4;
        unpack2(o2[r][0], o4.x, o4.y);
        unpack2(o2[r][1], o4.z, o4.w);
        if (degen) {
            o4.x = g_vmean[b * HD + tx * 4 + 0];
            o4.y = g_vmean[b * HD + tx * 4 + 1];
            o4.z = g_vmean[b * HD + tx * 4 + 2];
            o4.w = g_vmean[b * HD + tx * 4 + 3];
        } else {
            o4.x *= invl; o4.y *= invl; o4.z *= invl; o4.w *= invl;
        }
        *reinterpret_cast<float4*>(
            &out[((size_t)b * SEQ + q0 + row) * HD + tx * 4]) = o4;
    }
}

// ---------------------------------------------------------------------------
extern "C" void kernel_launch(void* const* d_in, const int* in_sizes, int n_in,
                              void* d_out, int out_size)
{
    const float* x   = (const float*)d_in[0];
    const int*   pad = (const int*)  d_in[1];
    const float* Wq  = (const float*)d_in[2];
    const float* Wk  = (const float*)d_in[3];
    const float* Wv  = (const float*)d_in[4];
    float* out = (float*)d_out;

    cudaFuncSetAttribute(attn_kernel,
                         cudaFuncAttributeMaxDynamicSharedMemorySize, ATTN_SMEM);

    qkv_kernel<<<dim3((BSZ * SEQ) / 128, 3), 128>>>(x, Wq, Wk, Wv);
    vmean_kernel<<<BSZ, 256>>>();
    attn_kernel<<<dim3(4 * 64), 128, ATTN_SMEM>>>(pad, out);
}